// round 11
// baseline (speedup 1.0000x reference)
#include <cuda_runtime.h>
#include <cstdint>

#define N_ 128
#define C_ 128
#define H_ 56
#define W_ 56
#define O_ 32
#define KTOT 384              // (tap, c) flattened: k = tap*128 + c

#define THREADS 640           // 16 compute warps + 4 stager warps
#define NCW 16                // compute warps
#define ROWS8 8
#define C_CH 32
#define NCH 4

// A smem: row = (k>>3)*4 + (k&3), 72 words/row (mi0: 0..31, mi1: 32..63, pad)
#define SA_STRIDE 72
#define SA_ROWS  (KTOT / 8 * 4)                // 192
#define SA_FLOATS (SA_ROWS * SA_STRIDE)        // 13824
#define SX_STRIDE 72
#define SX_ROW   (C_CH * SX_STRIDE)            // 2304 floats per h-row per chunk
#define SX_BUF   (ROWS8 * SX_ROW)              // 18432 floats
#define SMEM_BYTES ((SA_FLOATS + 2 * SX_BUF) * 4)   // 202752 B

__device__ __align__(16) float g_packA[SA_FLOATS];   // pre-transformed A, tf32-rounded

extern __shared__ float smf[];

__device__ __forceinline__ void cp16(float* dst, const float* src) {
    unsigned int d = (unsigned int)__cvta_generic_to_shared(dst);
    asm volatile("cp.async.ca.shared.global [%0], [%1], 16;" :: "r"(d), "l"(src));
}
__device__ __forceinline__ uint32_t f2tf32(float v) {
    uint32_t b;
    asm("cvt.rna.tf32.f32 %0, %1;" : "=r"(b) : "f"(v));
    return b;
}
__device__ __forceinline__ void mma8(float* d, uint32_t a0, uint32_t a1, uint32_t a2,
                                     uint32_t a3, uint32_t b0, uint32_t b1) {
    asm volatile(
        "mma.sync.aligned.m16n8k8.row.col.f32.tf32.tf32.f32 "
        "{%0,%1,%2,%3}, {%4,%5,%6,%7}, {%8,%9}, {%0,%1,%2,%3};"
        : "+f"(d[0]), "+f"(d[1]), "+f"(d[2]), "+f"(d[3])
        : "r"(a0), "r"(a1), "r"(a2), "r"(a3), "r"(b0), "r"(b1));
}

__global__ void prep_kernel(const float* __restrict__ wgt) {
    int idx = blockIdx.x * blockDim.x + threadIdx.x;
    if (idx < KTOT * O_) {
        int k = idx >> 5, m = idx & 31;
        int tap = k >> 7, c = k & 127;
        int row  = (k >> 3) * 4 + (k & 3);
        int word = (m >> 4) * 32 + 4 * (m & 7) + ((m & 15) >> 3) + 2 * ((k & 7) >> 2);
        g_packA[row * SA_STRIDE + word] =
            __uint_as_float(f2tf32(wgt[(m * C_ + c) * 3 + tap]));
    }
}

__global__ void __launch_bounds__(THREADS, 1)
conv_mma_kernel(const float* __restrict__ x, float* __restrict__ out) {
    float* sA  = smf;                    // repacked A
    float* sX0 = smf + SA_FLOATS;        // [r][c_loc][SX_STRIDE]; value w at idx w+4
    float* sX1 = sX0 + SX_BUF;

    const int n   = blockIdx.x;
    const int bh  = blockIdx.y;
    const int tid = threadIdx.x;
    const int wid  = tid >> 5;
    const int lane = tid & 31;
    const bool isStager = (wid >= NCW);

    // compute-warp coords
    const int r = wid >> 1;              // 0..7 h-row
    const int s = wid & 1;               // px half
    const int g = lane >> 2;
    const int t = lane & 3;
    const int h = bh * ROWS8 + r;

    // ---- A stage (all threads), own group ----
    for (int q = tid; q < SA_FLOATS / 4; q += THREADS)
        cp16(sA + q * 4, g_packA + q * 4);
    asm volatile("cp.async.commit_group;");

    // ---- zero pads: idx 3 (w=-1) and idx 60..71 ----
    for (int i = tid; i < 2 * ROWS8 * C_CH; i += THREADS) {
        float* row = sX0 + i * SX_STRIDE;          // sX0/sX1 contiguous
        row[3] = 0.0f;
#pragma unroll
        for (int z = 60; z < 72; ++z) row[z] = 0.0f;
    }

    // ---- stager-only chunk staging: 3584 cp16 / 128 threads = 28 each ----
    auto stage = [&](float* buf, int ch) {
        int st = tid - NCW * 32;
#pragma unroll
        for (int i = 0; i < (ROWS8 * C_CH * 14) / 128; ++i) {
            int q  = st + i * 128;
            int j  = q % 14;
            int cl = (q / 14) & 31;
            int r2 = q / (14 * 32);
            int hs = bh * ROWS8 + r2 - 1; if (hs < 0) hs += H_;
            const float* src = x + (((size_t)n * C_ + (ch * 32 + cl)) * H_ + hs) * W_ + j * 4;
            cp16(buf + (r2 * 32 + cl) * SX_STRIDE + 4 + j * 4, src);
        }
    };

    if (isStager) {
        stage(sX0, 0);
        asm volatile("cp.async.commit_group;");
    } else {
        asm volatile("cp.async.wait_group 0;");    // A landed (compute threads)
    }

    float acc[2][4][4];
#pragma unroll
    for (int mi = 0; mi < 2; ++mi)
#pragma unroll
        for (int ni = 0; ni < 4; ++ni)
#pragma unroll
            for (int e = 0; e < 4; ++e) acc[mi][ni][e] = 0.0f;

    const int baseB = 28 * s + g + 3;

    for (int ch = 0; ch < NCH; ++ch) {
        __syncthreads();                 // compute(ch-1) done -> buffer(ch+1) free
        if (isStager) {
            if (ch + 1 < NCH) {
                stage((ch & 1) ? sX0 : sX1, ch + 1);
                asm volatile("cp.async.commit_group;");
                asm volatile("cp.async.wait_group 1;");   // chunk ch landed
            } else {
                asm volatile("cp.async.wait_group 0;");
            }
        }
        __syncthreads();                 // chunk ch visible block-wide

        if (!isStager) {
            const float* buf = (ch & 1) ? sX1 : sX0;
            const float* sx  = buf + r * SX_ROW;

#pragma unroll
            for (int tap = 0; tap < 3; ++tap) {
#pragma unroll
                for (int ks = 0; ks < 4; ++ks) {
                    const int k8g = tap * 16 + ch * 4 + ks;
                    const int arow = (k8g * 4 + t) * SA_STRIDE + 4 * g;
                    uint4 A0 = *reinterpret_cast<const uint4*>(sA + arow);        // mi=0
                    uint4 A1 = *reinterpret_cast<const uint4*>(sA + arow + 32);   // mi=1

                    const int br = (ks * 8 + t) * SX_STRIDE + baseB + tap;
                    uint32_t b0[4], b1[4];
#pragma unroll
                    for (int ni = 0; ni < 4; ++ni) {
                        b0[ni] = __float_as_uint(sx[br + 8 * ni]);
                        b1[ni] = __float_as_uint(sx[br + 8 * ni + 4 * SX_STRIDE]);
                    }
#pragma unroll
                    for (int ni = 0; ni < 4; ++ni) {
                        mma8(acc[0][ni], A0.x, A0.y, A0.z, A0.w, b0[ni], b1[ni]);
                        mma8(acc[1][ni], A1.x, A1.y, A1.z, A1.w, b0[ni], b1[ni]);
                    }
                }
            }
        }
    }

    // ---- store: lane (g,t) row o=16mi+g (+8), col px = 28s + 8ni + 2t (+1) ----
    if (!isStager) {
#pragma unroll
        for (int mi = 0; mi < 2; ++mi)
#pragma unroll
            for (int ni = 0; ni < 4; ++ni) {
                if (ni == 3 && t >= 2) continue;
                int o  = 16 * mi + g;
                int px = 28 * s + 8 * ni + 2 * t;
                float* dst = out + (((size_t)n * O_ + o) * H_ + h) * W_ + px;
                *reinterpret_cast<float2*>(dst) =
                    make_float2(acc[mi][ni][0], acc[mi][ni][1]);
                *reinterpret_cast<float2*>(dst + 8 * H_ * W_) =
                    make_float2(acc[mi][ni][2], acc[mi][ni][3]);   // o+8
            }
    }
}

extern "C" void kernel_launch(void* const* d_in, const int* in_sizes, int n_in,
                              void* d_out, int out_size) {
    const float* x = (const float*)d_in[0];
    const float* w = (const float*)d_in[1];
    if (n_in >= 2 && in_sizes[0] == O_ * C_ * 3) {
        const float* tmp = x; x = w; w = tmp;
    }
    float* out = (float*)d_out;

    prep_kernel<<<(KTOT * O_ + 255) / 256, 256>>>(w);

    cudaFuncSetAttribute(conv_mma_kernel,
                         cudaFuncAttributeMaxDynamicSharedMemorySize, SMEM_BYTES);
    dim3 grid(N_, H_ / ROWS8);   // 128 x 7
    conv_mma_kernel<<<grid, THREADS, SMEM_BYTES>>>(x, out);
}

// round 12
// speedup vs baseline: 2.3468x; 2.3468x over previous
#include <cuda_runtime.h>
#include <cstdint>

#define N_ 128
#define C_ 128
#define H_ 56
#define W_ 56
#define O_ 32
#define KTOT 384              // (tap, c) flattened: k = tap*128 + c

#define THREADS 256           // 8 warps: r = wid>>1 (4 h rows), s = wid&1 (px half)
#define ROWS4 4
#define C_CH 16
#define NCH 8

#define SA_STRIDE 40          // words; LDS.64 @ 40k+2g+16mi -> conflict-free per phase
#define SX_STRIDE 72          // words; 8t+g+const distinct over warp -> conflict-free
#define SX_ROW   (C_CH * SX_STRIDE)            // 1152 floats per h-row per chunk
#define SX_BUF   (ROWS4 * SX_ROW)              // 4608 floats
#define SA_FLOATS (KTOT * SA_STRIDE)           // 15360
#define SMEM_BYTES ((SA_FLOATS + 2 * SX_BUF) * 4)   // 98304 B -> 2 blocks/SM

__device__ __align__(16) float g_packA[KTOT * O_];   // [k][p] interleaved, tf32-rounded

extern __shared__ float smf[];

__device__ __forceinline__ void cp16(float* dst, const float* src) {
    unsigned int d = (unsigned int)__cvta_generic_to_shared(dst);
    asm volatile("cp.async.ca.shared.global [%0], [%1], 16;" :: "r"(d), "l"(src));
}
__device__ __forceinline__ uint32_t f2tf32(float v) {
    uint32_t b;
    asm("cvt.rna.tf32.f32 %0, %1;" : "=r"(b) : "f"(v));
    return b;
}
__device__ __forceinline__ void mma8(float* d, uint32_t a0, uint32_t a1, uint32_t a2,
                                     uint32_t a3, uint32_t b0, uint32_t b1) {
    asm volatile(
        "mma.sync.aligned.m16n8k8.row.col.f32.tf32.tf32.f32 "
        "{%0,%1,%2,%3}, {%4,%5,%6,%7}, {%8,%9}, {%0,%1,%2,%3};"
        : "+f"(d[0]), "+f"(d[1]), "+f"(d[2]), "+f"(d[3])
        : "r"(a0), "r"(a1), "r"(a2), "r"(a3), "r"(b0), "r"(b1));
}

__global__ void prep_kernel(const float* __restrict__ wgt) {
    int idx = blockIdx.x * blockDim.x + threadIdx.x;
    if (idx < KTOT * O_) {
        int k = idx >> 5, m = idx & 31;
        int tap = k >> 7, c = k & 127;
        int mi = m >> 4, mm = m & 15;
        int p  = 16 * mi + 2 * (mm & 7) + (mm >> 3);   // pair-interleaved
        g_packA[k * O_ + p] = __uint_as_float(f2tf32(wgt[(m * C_ + c) * 3 + tap]));
    }
}

__global__ void __launch_bounds__(THREADS, 2)
conv_mma_kernel(const float* __restrict__ x, float* __restrict__ out) {
    float* sA  = smf;                    // [k][SA_STRIDE], interleaved p within row
    float* sX0 = smf + SA_FLOATS;        // [r][c_loc][SX_STRIDE]; value w at idx w+4
    float* sX1 = sX0 + SX_BUF;

    const int n   = blockIdx.x;
    const int bh  = blockIdx.y;
    const int tid = threadIdx.x;
    const int wid  = tid >> 5;
    const int lane = tid & 31;
    const int r    = wid >> 1;           // 0..3 h-row
    const int s    = wid & 1;            // px half: 0 -> 0..27, 1 -> 28..55
    const int g    = lane >> 2;          // 0..7
    const int t    = lane & 3;           // 0..3
    const int h    = bh * ROWS4 + r;

    // ---- stage A (L2-resident packed weights): 3072 x 16B ----
    for (int q = tid; q < (KTOT * O_) / 4; q += THREADS) {
        int k = q >> 3, pg = (q & 7) * 4;
        cp16(sA + k * SA_STRIDE + pg, g_packA + k * O_ + pg);
    }
    asm volatile("cp.async.commit_group;");

    // ---- zero pads: idx 3 (w=-1) and idx 60..71 (w>=56 + overread slack) ----
    for (int i = tid; i < 2 * ROWS4 * C_CH; i += THREADS) {
        float* row = sX0 + i * SX_STRIDE;          // sX0/sX1 contiguous
        row[3] = 0.0f;
#pragma unroll
        for (int z = 60; z < 72; ++z) row[z] = 0.0f;
    }

    auto stage = [&](float* buf, int ch) {
        for (int q = tid; q < ROWS4 * C_CH * 14; q += THREADS) {
            int j  = q % 14;
            int cl = (q / 14) & (C_CH - 1);
            int r2 = q / (14 * C_CH);
            int hs = bh * ROWS4 + r2 - 1; if (hs < 0) hs += H_;
            const float* src = x + (((size_t)n * C_ + (ch * C_CH + cl)) * H_ + hs) * W_ + j * 4;
            cp16(buf + (r2 * C_CH + cl) * SX_STRIDE + 4 + j * 4, src);
        }
    };

    stage(sX0, 0);
    asm volatile("cp.async.commit_group;");

    float acc[2][4][4];
#pragma unroll
    for (int mi = 0; mi < 2; ++mi)
#pragma unroll
        for (int ni = 0; ni < 4; ++ni)
#pragma unroll
            for (int e = 0; e < 4; ++e) acc[mi][ni][e] = 0.0f;

    const int baseB = 28 * s + g + 3;

    for (int ch = 0; ch < NCH; ++ch) {
        __syncthreads();                          // prev compute done block-wide
        if (ch + 1 < NCH) stage((ch & 1) ? sX0 : sX1, ch + 1);
        asm volatile("cp.async.commit_group;");
        if (ch < NCH - 1) asm volatile("cp.async.wait_group 1;");
        else              asm volatile("cp.async.wait_group 0;");
        __syncthreads();                          // chunk ch (+A) visible

        const float* buf = (ch & 1) ? sX1 : sX0;
        const float* sx  = buf + r * SX_ROW;

#pragma unroll
        for (int tap = 0; tap < 3; ++tap) {
#pragma unroll
            for (int ks = 0; ks < 2; ++ks) {
                const int kg = tap * 128 + ch * C_CH + ks * 8;
                const uint32_t* ua = (const uint32_t*)sA;
                const int ar = (kg + t) * SA_STRIDE + 2 * g;

                uint2 A0  = *(const uint2*)(ua + ar);                   // mi=0, k_lo
                uint2 A0h = *(const uint2*)(ua + ar + 4 * SA_STRIDE);   // mi=0, k_hi
                uint2 A1  = *(const uint2*)(ua + ar + 16);              // mi=1, k_lo
                uint2 A1h = *(const uint2*)(ua + ar + 16 + 4 * SA_STRIDE);

                const int br = (ks * 8 + t) * SX_STRIDE + baseB + tap;
                uint32_t b0[4], b1[4];
#pragma unroll
                for (int ni = 0; ni < 4; ++ni) {
                    b0[ni] = __float_as_uint(sx[br + 8 * ni]);
                    b1[ni] = __float_as_uint(sx[br + 8 * ni + 4 * SX_STRIDE]);
                }
#pragma unroll
                for (int ni = 0; ni < 4; ++ni) {
                    mma8(acc[0][ni], A0.x, A0.y, A0h.x, A0h.y, b0[ni], b1[ni]);
                    mma8(acc[1][ni], A1.x, A1.y, A1h.x, A1h.y, b0[ni], b1[ni]);
                }
            }
        }
    }

    // ---- store: lane (g,t) row o=16mi+g (+8), col px = 28s + 8ni + 2t (+1) ----
#pragma unroll
    for (int mi = 0; mi < 2; ++mi)
#pragma unroll
        for (int ni = 0; ni < 4; ++ni) {
            if (ni == 3 && t >= 2) continue;      // local px 28..31: other half / OOB
            int o  = 16 * mi + g;
            int px = 28 * s + 8 * ni + 2 * t;
            float* dst = out + (((size_t)n * O_ + o) * H_ + h) * W_ + px;
            *reinterpret_cast<float2*>(dst) =
                make_float2(acc[mi][ni][0], acc[mi][ni][1]);
            *reinterpret_cast<float2*>(dst + 8 * H_ * W_) =
                make_float2(acc[mi][ni][2], acc[mi][ni][3]);   // o+8
        }
}

extern "C" void kernel_launch(void* const* d_in, const int* in_sizes, int n_in,
                              void* d_out, int out_size) {
    const float* x = (const float*)d_in[0];
    const float* w = (const float*)d_in[1];
    if (n_in >= 2 && in_sizes[0] == O_ * C_ * 3) {
        const float* tmp = x; x = w; w = tmp;
    }
    float* out = (float*)d_out;

    prep_kernel<<<(KTOT * O_ + 255) / 256, 256>>>(w);

    cudaFuncSetAttribute(conv_mma_kernel,
                         cudaFuncAttributeMaxDynamicSharedMemorySize, SMEM_BYTES);
    dim3 grid(N_, H_ / ROWS4);   // 128 x 14
    conv_mma_kernel<<<grid, THREADS, SMEM_BYTES>>>(x, out);
}